// round 11
// baseline (speedup 1.0000x reference)
#include <cuda_runtime.h>
#include <cstdint>

#define B_TOTAL 16384
#define F_FIELDS 39
#define E_DIM 64
#define U_DIM 128
#define BTILE 128
#define THREADS 640          // 16 consumer warps + 4 producer warps
#define NGRP  288            // row-blocked groups of 8 (rows padded to mult of 8)
#define KPAD  2304           // NGRP*8
#define NCHUNK 36
#define FSTR 65
#define ASTR 72
#define BSTR 72
// smem float offsets
#define OFF_A0 8336          // sF = 128*65 + 16 pad
#define OFF_A1 17552
#define OFF_B0 26768
#define OFF_B1 35984
#define OFF_G  45200
#define SMEM_FLOATS 45488
#define SMEM_BYTES  (SMEM_FLOATS * 4)   // 181952 B, 1 CTA/SM

// named barrier ids (0 reserved for __syncthreads)
#define FULL0 1
#define FULL1 2
#define EMPTY0 3
#define EMPTY1 4

__device__ float    g_fsum[B_TOTAL * E_DIM];
__device__ unsigned g_T[U_DIM * KPAD];   // rna-tf32 bits of packed symmetric W (perm layout)

__device__ __forceinline__ unsigned f2tf(float x) {
    unsigned y; asm("cvt.rna.tf32.f32 %0, %1;" : "=r"(y) : "f"(x)); return y;
}
__device__ __forceinline__ uint32_t smem_u32(const void* p) {
    uint32_t a;
    asm("{ .reg .u64 t; cvta.to.shared.u64 t, %1; cvt.u32.u64 %0, t; }" : "=r"(a) : "l"(p));
    return a;
}
__device__ __forceinline__ void cp16(uint32_t dst, const void* src) {
    asm volatile("cp.async.cg.shared.global [%0], [%1], 16;" :: "r"(dst), "l"(src) : "memory");
}
__device__ __forceinline__ void cp_commit() {
    asm volatile("cp.async.commit_group;" ::: "memory");
}
__device__ __forceinline__ void cp_wait0() {
    asm volatile("cp.async.wait_group 0;" ::: "memory");
}
__device__ __forceinline__ void bar_sync(int id) {
    asm volatile("bar.sync %0, %1;" :: "r"(id), "n"(THREADS) : "memory");
}
__device__ __forceinline__ void bar_arrive(int id) {
    asm volatile("bar.arrive %0, %1;" :: "r"(id), "n"(THREADS) : "memory");
}
__device__ __forceinline__ void mma8(float* c, unsigned a0, unsigned a1,
                                     unsigned a2, unsigned a3,
                                     unsigned b0, unsigned b1) {
    asm volatile(
        "mma.sync.aligned.m16n8k8.row.col.f32.tf32.tf32.f32 "
        "{%0,%1,%2,%3}, {%4,%5,%6,%7}, {%8,%9}, {%0,%1,%2,%3};"
        : "+f"(c[0]), "+f"(c[1]), "+f"(c[2]), "+f"(c[3])
        : "r"(a0), "r"(a1), "r"(a2), "r"(a3), "r"(b0), "r"(b1));
}

// group g -> (i<<8)|j0 : row-blocked upper-tri, rows padded to 8. 288 groups.
__device__ __forceinline__ unsigned grp_of(int g) {
    int cum = 0; unsigned val = 0;
#pragma unroll 1
    for (int r = 0; r < 64; ++r) {
        int ng = (71 - r) >> 3;
        if (g >= cum && g < cum + ng)
            val = ((unsigned)r << 8) | (unsigned)(r + 8 * (g - cum));
        cum += ng;
    }
    return val;
}

// ---------------- fused prep: feat_sum + packed symmetric T (perm layout) ----------------
__global__ void prep_kernel(const float* __restrict__ embeds,
                            const float* __restrict__ W) {
    if (blockIdx.x < 1024) {
        int idx = blockIdx.x * 256 + threadIdx.x;
        int b = idx >> 4;
        int e4 = idx & 15;
        const float4* p = reinterpret_cast<const float4*>(embeds)
                          + (size_t)b * (F_FIELDS * E_DIM / 4) + e4;
        float4 s = make_float4(0.f, 0.f, 0.f, 0.f);
#pragma unroll
        for (int f = 0; f < F_FIELDS; ++f) {
            float4 v = p[f * (E_DIM / 4)];
            s.x += v.x; s.y += v.y; s.z += v.z; s.w += v.w;
        }
        reinterpret_cast<float4*>(g_fsum)[idx] = s;
    } else {
        int idx = (blockIdx.x - 1024) * 256 + threadIdx.x;   // < 294912
        int u = idx / KPAD;
        int k = idx - u * KPAD;
        unsigned grp = grp_of(k >> 3);
        int n = k & 7;
        int o = (n >> 1) + ((n & 1) << 2);   // perm pos -> orig offset
        int i = grp >> 8;
        int j = (int)(grp & 255) + o;
        float v = 0.f;
        if (j < 64) {
            v = W[u * 4096 + i * 64 + j];
            if (i != j) v += W[u * 4096 + j * 64 + i];
        }
        g_T[idx] = f2tf(v);
    }
}

// ---------------- main GEMM: warp-specialized producer/consumer ----------------
// C[128b x 128u] += A[128 x 64k] * B[64k x 128], 36 chunks over padded K=2304.
// Warps 0-15: consumers (4m x 4n, 32x32 tiles) - frag LDS.64 + HMMA only.
// Warps 16-19: producers - row-blocked A-gen + cp.async B, 2-stage ring.
__global__ void __launch_bounds__(THREADS, 1)
quad_kernel(float* __restrict__ out) {
    extern __shared__ float sm[];
    float*    sF = sm;
    unsigned* sG = (unsigned*)(sm + OFF_G);

    const int tid  = threadIdx.x;
    const int lane = tid & 31;
    const int warp = tid >> 5;
    const int b0 = blockIdx.x * BTILE;

    // ---- cooperative staging of sF (stride 65, +16 zero pad) and sG ----
    for (int idx = tid; idx < 2048; idx += THREADS) {
        int row = idx >> 4, c4 = (idx & 15) << 2;
        float4 v = *reinterpret_cast<const float4*>(
            g_fsum + (size_t)(b0 + row) * E_DIM + c4);
        sF[row * FSTR + c4 + 0] = v.x;
        sF[row * FSTR + c4 + 1] = v.y;
        sF[row * FSTR + c4 + 2] = v.z;
        sF[row * FSTR + c4 + 3] = v.w;
    }
    if (tid < 16) sF[128 * FSTR + tid] = 0.f;   // pad: last row may read j up to 70
    if (tid < NGRP) sG[tid] = grp_of(tid);
    __syncthreads();

    if (warp >= 16) {
        // ================= PRODUCER (128 threads) =================
        const int p = tid - 512;               // 0..127 (A row)
        const float* fr = sF + p * FSTR;
        const uint32_t sB_base = smem_u32(sm + OFF_B0);

#pragma unroll 1
        for (int c = 0; c < NCHUNK; ++c) {
            const int s = c & 1;
            if (c >= 2) bar_sync(s ? EMPTY1 : EMPTY0);

            // cp.async B(c): 2048 float4, 16 per thread, coalesced
            {
                uint32_t dstb = sB_base + (uint32_t)(s ? 9216 * 4 : 0);
#pragma unroll
                for (int t = 0; t < 16; ++t) {
                    int idx = p + t * 128;           // float4 index
                    int row = idx >> 4, c4 = (idx & 15) << 2;
                    cp16(dstb + (uint32_t)(row * BSTR + c4) * 4u,
                         g_T + (size_t)row * KPAD + c * 64 + c4);
                }
                cp_commit();
            }
            // gen A(c): row p, 8 groups of 8 cols; uniform i per group
            {
                float* dst = sm + (s ? OFF_A1 : OFF_A0) + p * ASTR;
#pragma unroll
                for (int g8 = 0; g8 < 8; ++g8) {
                    unsigned grp = sG[c * 8 + g8];
                    const float fi = fr[grp >> 8];
                    const float* fj = fr + (grp & 255);
                    float t0 = fi * fj[0], t1 = fi * fj[1];
                    float t2 = fi * fj[2], t3 = fi * fj[3];
                    float t4 = fi * fj[4], t5 = fi * fj[5];
                    float t6 = fi * fj[6], t7 = fi * fj[7];
                    // perm: pos 2t <- orig t, pos 2t+1 <- orig t+4
                    uint4 v0 = make_uint4(f2tf(t0), f2tf(t4), f2tf(t1), f2tf(t5));
                    uint4 v1 = make_uint4(f2tf(t2), f2tf(t6), f2tf(t3), f2tf(t7));
                    *reinterpret_cast<uint4*>(dst + g8 * 8)     = v0;
                    *reinterpret_cast<uint4*>(dst + g8 * 8 + 4) = v1;
                }
            }
            cp_wait0();
            bar_arrive(s ? FULL1 : FULL0);
        }
    } else {
        // ================= CONSUMER (512 threads, 16 warps) =================
        const int l4 = lane >> 2, k4 = lane & 3;
        const int row_base = (warp & 3) * 32;     // 4-way m split
        const int col_base = (warp >> 2) * 32;    // 4-way n split

        float acc[2][4][4];
#pragma unroll
        for (int mt = 0; mt < 2; ++mt)
#pragma unroll
            for (int nt = 0; nt < 4; ++nt)
#pragma unroll
                for (int x = 0; x < 4; ++x) acc[mt][nt][x] = 0.f;

#pragma unroll 1
        for (int c = 0; c < NCHUNK; ++c) {
            const int s = c & 1;
            bar_sync(s ? FULL1 : FULL0);

            const float* A = sm + (s ? OFF_A1 : OFF_A0);
            const float* B = sm + (s ? OFF_B1 : OFF_B0);
#pragma unroll
            for (int kk = 0; kk < 8; ++kk) {
                const int kcol = kk * 8 + k4 * 2;
                float2 a0[2], a1[2];
#pragma unroll
                for (int mt = 0; mt < 2; ++mt) {
                    const float* ap = A + (row_base + mt * 16 + l4) * ASTR + kcol;
                    a0[mt] = *reinterpret_cast<const float2*>(ap);
                    a1[mt] = *reinterpret_cast<const float2*>(ap + 8 * ASTR);
                }
#pragma unroll
                for (int nt = 0; nt < 4; ++nt) {
                    float2 bb = *reinterpret_cast<const float2*>(
                        B + (col_base + nt * 8 + l4) * BSTR + kcol);
                    unsigned bf0 = __float_as_uint(bb.x);
                    unsigned bf1 = __float_as_uint(bb.y);
#pragma unroll
                    for (int mt = 0; mt < 2; ++mt)
                        mma8(acc[mt][nt],
                             __float_as_uint(a0[mt].x), __float_as_uint(a1[mt].x),
                             __float_as_uint(a0[mt].y), __float_as_uint(a1[mt].y),
                             bf0, bf1);
                }
            }
            bar_arrive(s ? EMPTY1 : EMPTY0);
        }

        // ---- epilogue: direct STG ----
#pragma unroll
        for (int mt = 0; mt < 2; ++mt) {
#pragma unroll
            for (int nt = 0; nt < 4; ++nt) {
                const int rr = b0 + row_base + mt * 16 + l4;
                const int cc = col_base + nt * 8 + k4 * 2;
                float2 v0 = make_float2(acc[mt][nt][0], acc[mt][nt][1]);
                float2 v1 = make_float2(acc[mt][nt][2], acc[mt][nt][3]);
                *reinterpret_cast<float2*>(out + (size_t)rr * U_DIM + cc) = v0;
                *reinterpret_cast<float2*>(out + (size_t)(rr + 8) * U_DIM + cc) = v1;
            }
        }
    }
}

extern "C" void kernel_launch(void* const* d_in, const int* in_sizes, int n_in,
                              void* d_out, int out_size) {
    const float* embeds = (const float*)d_in[0];   // (16384, 39, 64)
    const float* W      = (const float*)d_in[1];   // (128, 64, 64)
    float* out          = (float*)d_out;           // (16384, 128)

    static int smem_set = 0;
    if (!smem_set) {
        cudaFuncSetAttribute(quad_kernel,
                             cudaFuncAttributeMaxDynamicSharedMemorySize, SMEM_BYTES);
        smem_set = 1;
    }

    prep_kernel<<<1024 + (U_DIM * KPAD) / 256, 256>>>(embeds, W);
    quad_kernel<<<B_TOTAL / BTILE, THREADS, SMEM_BYTES>>>(out);
}

// round 13
// speedup vs baseline: 1.0312x; 1.0312x over previous
#include <cuda_runtime.h>
#include <cstdint>

#define B_TOTAL 16384
#define F_FIELDS 39
#define E_DIM 64
#define U_DIM 128
#define BTILE 128
#define THREADS 640          // 16 consumer warps (8 tiles x 2 ksplit) + 4 producers
#define NGRP  288
#define KPAD  2304           // NGRP*8
#define NCHUNK 36
#define FSTR 65
#define ASTR 72
#define BSTR 72
// smem float offsets
#define OFF_A0 8336          // sF = 128*65 + 16 pad
#define OFF_A1 17552
#define OFF_B0 26768
#define OFF_B1 35984
#define OFF_G  45200
#define SMEM_FLOATS 45488
#define SMEM_BYTES  (SMEM_FLOATS * 4)   // 181952 B, 1 CTA/SM

// named barrier ids (0 reserved for __syncthreads)
#define FULL0 1
#define FULL1 2
#define EMPTY0 3
#define EMPTY1 4
#define CONS   5

__device__ float    g_fsum[B_TOTAL * E_DIM];
__device__ unsigned g_T[U_DIM * KPAD];   // rna-tf32 bits of packed symmetric W (perm layout)

__device__ __forceinline__ unsigned f2tf(float x) {
    unsigned y; asm("cvt.rna.tf32.f32 %0, %1;" : "=r"(y) : "f"(x)); return y;
}
__device__ __forceinline__ uint32_t smem_u32(const void* p) {
    uint32_t a;
    asm("{ .reg .u64 t; cvta.to.shared.u64 t, %1; cvt.u32.u64 %0, t; }" : "=r"(a) : "l"(p));
    return a;
}
__device__ __forceinline__ void cp16(uint32_t dst, const void* src) {
    asm volatile("cp.async.cg.shared.global [%0], [%1], 16;" :: "r"(dst), "l"(src) : "memory");
}
__device__ __forceinline__ void cp_commit() {
    asm volatile("cp.async.commit_group;" ::: "memory");
}
__device__ __forceinline__ void cp_wait0() {
    asm volatile("cp.async.wait_group 0;" ::: "memory");
}
__device__ __forceinline__ void bar_sync(int id, int cnt) {
    asm volatile("bar.sync %0, %1;" :: "r"(id), "r"(cnt) : "memory");
}
__device__ __forceinline__ void bar_arrive(int id, int cnt) {
    asm volatile("bar.arrive %0, %1;" :: "r"(id), "r"(cnt) : "memory");
}
__device__ __forceinline__ void mma8(float* c, unsigned a0, unsigned a1,
                                     unsigned a2, unsigned a3,
                                     unsigned b0, unsigned b1) {
    asm volatile(
        "mma.sync.aligned.m16n8k8.row.col.f32.tf32.tf32.f32 "
        "{%0,%1,%2,%3}, {%4,%5,%6,%7}, {%8,%9}, {%0,%1,%2,%3};"
        : "+f"(c[0]), "+f"(c[1]), "+f"(c[2]), "+f"(c[3])
        : "r"(a0), "r"(a1), "r"(a2), "r"(a3), "r"(b0), "r"(b1));
}

// group g -> (i<<8)|j0 : row-blocked upper-tri, rows padded to 8. 288 groups.
// Block x holds rows 8x..8x+7, each with (8-x) groups.
// Groups before block x: cum(x) = 8*(8x - x(x-1)/2)  -> {0,64,120,168,208,240,264,280}.
// FIX vs R12: compare g against ABSOLUTE prefix sums (the incremental version
// re-tested with stale cum and advanced wrongly for g in upper block halves).
__device__ __forceinline__ unsigned grp_of(int g) {
    int b = 0;
#pragma unroll
    for (int x = 1; x <= 7; ++x) {
        int cumx = 8 * (8 * x - ((x * (x - 1)) >> 1));
        if (g >= cumx) b = x;
    }
    int cum = 8 * (8 * b - ((b * (b - 1)) >> 1));
    int idx = g - cum;
    int ng = 8 - b;
    int ro = idx / ng;
    int jg = idx - ro * ng;
    int r = 8 * b + ro;
    return ((unsigned)r << 8) | (unsigned)(r + 8 * jg);
}

// ---------------- fused prep: feat_sum + packed symmetric T (perm layout) ----------------
__global__ void prep_kernel(const float* __restrict__ embeds,
                            const float* __restrict__ W) {
    if (blockIdx.x < 1024) {
        int idx = blockIdx.x * 256 + threadIdx.x;
        int b = idx >> 4;
        int e4 = idx & 15;
        const float4* p = reinterpret_cast<const float4*>(embeds)
                          + (size_t)b * (F_FIELDS * E_DIM / 4) + e4;
        float4 s = make_float4(0.f, 0.f, 0.f, 0.f);
#pragma unroll
        for (int f = 0; f < F_FIELDS; ++f) {
            float4 v = p[f * (E_DIM / 4)];
            s.x += v.x; s.y += v.y; s.z += v.z; s.w += v.w;
        }
        reinterpret_cast<float4*>(g_fsum)[idx] = s;
    } else {
        int idx = (blockIdx.x - 1024) * 256 + threadIdx.x;   // < 294912
        int u = idx / KPAD;
        int k = idx - u * KPAD;
        unsigned grp = grp_of(k >> 3);
        int n = k & 7;
        int o = (n >> 1) + ((n & 1) << 2);   // perm pos -> orig offset
        int i = grp >> 8;
        int j = (int)(grp & 255) + o;
        float v = 0.f;
        if (j < 64) {
            v = W[u * 4096 + i * 64 + j];
            if (i != j) v += W[u * 4096 + j * 64 + i];
        }
        g_T[idx] = f2tf(v);
    }
}

// ---------------- main GEMM: warp-specialized producer/consumer ----------------
// C[128b x 128u] += A[128 x 64k] * B[64k x 128], 36 chunks over padded K=2304.
// Warps 0-15: consumers = 8 tile-warps (4m x 2n, 32x64) x 2 k-split (kk halves).
// Warps 16-19: producers - row-blocked A-gen + cp.async B, 2-stage ring.
__global__ void __launch_bounds__(THREADS, 1)
quad_kernel(float* __restrict__ out) {
    extern __shared__ float sm[];
    float*    sF = sm;
    unsigned* sG = (unsigned*)(sm + OFF_G);

    const int tid  = threadIdx.x;
    const int lane = tid & 31;
    const int warp = tid >> 5;
    const int b0 = blockIdx.x * BTILE;

    // ---- cooperative staging of sF (stride 65, +16 zero pad) and sG ----
    for (int idx = tid; idx < 2048; idx += THREADS) {
        int row = idx >> 4, c4 = (idx & 15) << 2;
        float4 v = *reinterpret_cast<const float4*>(
            g_fsum + (size_t)(b0 + row) * E_DIM + c4);
        sF[row * FSTR + c4 + 0] = v.x;
        sF[row * FSTR + c4 + 1] = v.y;
        sF[row * FSTR + c4 + 2] = v.z;
        sF[row * FSTR + c4 + 3] = v.w;
    }
    if (tid < 16) sF[128 * FSTR + tid] = 0.f;   // pad: last row may read j up to 70
    if (tid < NGRP) sG[tid] = grp_of(tid);
    __syncthreads();

    if (warp >= 16) {
        // ================= PRODUCER (128 threads) =================
        const int p = tid - 512;               // 0..127 (A row)
        const float* fr = sF + p * FSTR;
        const uint32_t sB_base = smem_u32(sm + OFF_B0);

#pragma unroll 1
        for (int c = 0; c < NCHUNK; ++c) {
            const int s = c & 1;
            if (c >= 2) bar_sync(s ? EMPTY1 : EMPTY0, THREADS);

            // cp.async B(c): 2048 float4, 16 per thread, coalesced
            {
                uint32_t dstb = sB_base + (uint32_t)(s ? 9216 * 4 : 0);
#pragma unroll
                for (int t = 0; t < 16; ++t) {
                    int idx = p + t * 128;           // float4 index
                    int row = idx >> 4, c4 = (idx & 15) << 2;
                    cp16(dstb + (uint32_t)(row * BSTR + c4) * 4u,
                         g_T + (size_t)row * KPAD + c * 64 + c4);
                }
                cp_commit();
            }
            // gen A(c): row p, 8 groups of 8 cols; uniform i per group
            {
                float* dst = sm + (s ? OFF_A1 : OFF_A0) + p * ASTR;
#pragma unroll
                for (int g8 = 0; g8 < 8; ++g8) {
                    unsigned grp = sG[c * 8 + g8];
                    const float fi = fr[grp >> 8];
                    const float* fj = fr + (grp & 255);
                    float t0 = fi * fj[0], t1 = fi * fj[1];
                    float t2 = fi * fj[2], t3 = fi * fj[3];
                    float t4 = fi * fj[4], t5 = fi * fj[5];
                    float t6 = fi * fj[6], t7 = fi * fj[7];
                    // perm: pos 2t <- orig t, pos 2t+1 <- orig t+4
                    uint4 v0 = make_uint4(f2tf(t0), f2tf(t4), f2tf(t1), f2tf(t5));
                    uint4 v1 = make_uint4(f2tf(t2), f2tf(t6), f2tf(t3), f2tf(t7));
                    *reinterpret_cast<uint4*>(dst + g8 * 8)     = v0;
                    *reinterpret_cast<uint4*>(dst + g8 * 8 + 4) = v1;
                }
            }
            cp_wait0();
            bar_arrive(s ? FULL1 : FULL0, THREADS);
        }
    } else {
        // ================= CONSUMER (512 threads, 16 warps) =================
        const int l4 = lane >> 2, k4 = lane & 3;
        const int twarp = warp & 7;
        const int kw    = warp >> 3;              // k-split half
        const int row_base = (twarp & 3) * 32;    // 4-way m split
        const int col_base = (twarp >> 2) * 64;   // 2-way n split

        float acc[2][8][4];
#pragma unroll
        for (int mt = 0; mt < 2; ++mt)
#pragma unroll
            for (int nt = 0; nt < 8; ++nt)
#pragma unroll
                for (int x = 0; x < 4; ++x) acc[mt][nt][x] = 0.f;

#pragma unroll 1
        for (int c = 0; c < NCHUNK; ++c) {
            const int s = c & 1;
            bar_sync(s ? FULL1 : FULL0, THREADS);

            const float* A = sm + (s ? OFF_A1 : OFF_A0);
            const float* B = sm + (s ? OFF_B1 : OFF_B0);
#pragma unroll
            for (int kx = 0; kx < 4; ++kx) {
                const int kcol = (kw * 4 + kx) * 8 + k4 * 2;
                float2 a0[2], a1[2];
#pragma unroll
                for (int mt = 0; mt < 2; ++mt) {
                    const float* ap = A + (row_base + mt * 16 + l4) * ASTR + kcol;
                    a0[mt] = *reinterpret_cast<const float2*>(ap);
                    a1[mt] = *reinterpret_cast<const float2*>(ap + 8 * ASTR);
                }
#pragma unroll
                for (int nt = 0; nt < 8; ++nt) {
                    float2 bb = *reinterpret_cast<const float2*>(
                        B + (col_base + nt * 8 + l4) * BSTR + kcol);
                    unsigned bf0 = __float_as_uint(bb.x);
                    unsigned bf1 = __float_as_uint(bb.y);
#pragma unroll
                    for (int mt = 0; mt < 2; ++mt)
                        mma8(acc[mt][nt],
                             __float_as_uint(a0[mt].x), __float_as_uint(a1[mt].x),
                             __float_as_uint(a0[mt].y), __float_as_uint(a1[mt].y),
                             bf0, bf1);
                }
            }
            bar_arrive(s ? EMPTY1 : EMPTY0, THREADS);
        }

        // ---- epilogue: sum k-split partials via smem, then STG ----
        // Barrier first: all consumers must be done reading stage A/B before
        // sRed (which aliases A0+A1) is written.
        bar_sync(CONS, 512);
        float4* sRed = reinterpret_cast<float4*>(sm + OFF_A0);   // 16*256 float4 = 64 KB
        if (kw == 1) {
            const int idx = tid - 256;
#pragma unroll
            for (int mt = 0; mt < 2; ++mt)
#pragma unroll
                for (int nt = 0; nt < 8; ++nt) {
                    int q = mt * 8 + nt;
                    sRed[q * 256 + idx] = make_float4(acc[mt][nt][0], acc[mt][nt][1],
                                                      acc[mt][nt][2], acc[mt][nt][3]);
                }
        }
        bar_sync(CONS, 512);
        if (kw == 0) {
#pragma unroll
            for (int mt = 0; mt < 2; ++mt) {
#pragma unroll
                for (int nt = 0; nt < 8; ++nt) {
                    int q = mt * 8 + nt;
                    float4 p = sRed[q * 256 + tid];
                    float2 v0 = make_float2(acc[mt][nt][0] + p.x, acc[mt][nt][1] + p.y);
                    float2 v1 = make_float2(acc[mt][nt][2] + p.z, acc[mt][nt][3] + p.w);
                    const int rr = b0 + row_base + mt * 16 + l4;
                    const int cc = col_base + nt * 8 + k4 * 2;
                    *reinterpret_cast<float2*>(out + (size_t)rr * U_DIM + cc) = v0;
                    *reinterpret_cast<float2*>(out + (size_t)(rr + 8) * U_DIM + cc) = v1;
                }
            }
        }
    }
}

extern "C" void kernel_launch(void* const* d_in, const int* in_sizes, int n_in,
                              void* d_out, int out_size) {
    const float* embeds = (const float*)d_in[0];   // (16384, 39, 64)
    const float* W      = (const float*)d_in[1];   // (128, 64, 64)
    float* out          = (float*)d_out;           // (16384, 128)

    static int smem_set = 0;
    if (!smem_set) {
        cudaFuncSetAttribute(quad_kernel,
                             cudaFuncAttributeMaxDynamicSharedMemorySize, SMEM_BYTES);
        smem_set = 1;
    }

    prep_kernel<<<1024 + (U_DIM * KPAD) / 256, 256>>>(embeds, W);
    quad_kernel<<<B_TOTAL / BTILE, THREADS, SMEM_BYTES>>>(out);
}

// round 14
// speedup vs baseline: 1.4643x; 1.4200x over previous
#include <cuda_runtime.h>
#include <cuda_fp16.h>
#include <cstdint>

#define B_TOTAL 16384
#define F_FIELDS 39
#define E_DIM 64
#define U_DIM 128
#define BTILE 128
#define THREADS 640          // 16 consumer warps (8 tiles x 2 ksplit) + 4 producers
#define NGRP  288
#define KPAD  2304           // NGRP*8
#define NCHUNK 36
#define FSTR 65
#define RSTR 40              // row stride in b32 words (32 data + 8 pad) for A/B stages
// smem word(=float) offsets
#define OFF_A0 8336          // sF = 128*65 + 16 pad
#define OFF_A1 13456
#define OFF_B0 18576
#define OFF_B1 23696
#define OFF_G  28816
#define SMEM_FLOATS 29104
#define SMEM_BYTES  (SMEM_FLOATS * 4)   // 116416 B, 1 CTA/SM

// named barrier ids (0 reserved for __syncthreads)
#define FULL0 1
#define FULL1 2
#define EMPTY0 3
#define EMPTY1 4
#define CONS   5

__device__ float  g_fsum[B_TOTAL * E_DIM];
__device__ __half g_T[U_DIM * KPAD];   // rn(fp16) packed symmetric W, perm layout

__device__ __forceinline__ uint32_t smem_u32(const void* p) {
    uint32_t a;
    asm("{ .reg .u64 t; cvta.to.shared.u64 t, %1; cvt.u32.u64 %0, t; }" : "=r"(a) : "l"(p));
    return a;
}
__device__ __forceinline__ void cp16(uint32_t dst, const void* src) {
    asm volatile("cp.async.cg.shared.global [%0], [%1], 16;" :: "r"(dst), "l"(src) : "memory");
}
__device__ __forceinline__ void cp_commit() {
    asm volatile("cp.async.commit_group;" ::: "memory");
}
__device__ __forceinline__ void cp_wait0() {
    asm volatile("cp.async.wait_group 0;" ::: "memory");
}
__device__ __forceinline__ void bar_sync(int id, int cnt) {
    asm volatile("bar.sync %0, %1;" :: "r"(id), "r"(cnt) : "memory");
}
__device__ __forceinline__ void bar_arrive(int id, int cnt) {
    asm volatile("bar.arrive %0, %1;" :: "r"(id), "r"(cnt) : "memory");
}
// fp16 mma: D(16x8,f32) += A(16x16,f16) * B(16x8,f16)
__device__ __forceinline__ void mma16(float* c, unsigned a0, unsigned a1,
                                      unsigned a2, unsigned a3,
                                      unsigned b0, unsigned b1) {
    asm volatile(
        "mma.sync.aligned.m16n8k16.row.col.f32.f16.f16.f32 "
        "{%0,%1,%2,%3}, {%4,%5,%6,%7}, {%8,%9}, {%0,%1,%2,%3};"
        : "+f"(c[0]), "+f"(c[1]), "+f"(c[2]), "+f"(c[3])
        : "r"(a0), "r"(a1), "r"(a2), "r"(a3), "r"(b0), "r"(b1));
}

// group g -> (i<<8)|j0 : row-blocked upper-tri, rows padded to 8. 288 groups.
// cum(x) = 8*(8x - x(x-1)/2) -> {0,64,120,168,208,240,264,280}. Absolute-prefix compare.
__device__ __forceinline__ unsigned grp_of(int g) {
    int b = 0;
#pragma unroll
    for (int x = 1; x <= 7; ++x) {
        int cumx = 8 * (8 * x - ((x * (x - 1)) >> 1));
        if (g >= cumx) b = x;
    }
    int cum = 8 * (8 * b - ((b * (b - 1)) >> 1));
    int idx = g - cum;
    int ng = 8 - b;
    int ro = idx / ng;
    int jg = idx - ro * ng;
    int r = 8 * b + ro;
    return ((unsigned)r << 8) | (unsigned)(r + 8 * jg);
}

// ---------------- fused prep: feat_sum + packed symmetric T (fp16, perm layout) ----
// k_mem decode: chunk c=k/64, step s, word w=(k%16)/2, h=k&1;
// logical pair = w/2 + (w&1)*4; group = c*8 + s*2 + (pair>=4); off = (pair&3)*2+h.
__global__ void prep_kernel(const float* __restrict__ embeds,
                            const float* __restrict__ W) {
    if (blockIdx.x < 1024) {
        int idx = blockIdx.x * 256 + threadIdx.x;
        int b = idx >> 4;
        int e4 = idx & 15;
        const float4* p = reinterpret_cast<const float4*>(embeds)
                          + (size_t)b * (F_FIELDS * E_DIM / 4) + e4;
        float4 s = make_float4(0.f, 0.f, 0.f, 0.f);
#pragma unroll
        for (int f = 0; f < F_FIELDS; ++f) {
            float4 v = p[f * (E_DIM / 4)];
            s.x += v.x; s.y += v.y; s.z += v.z; s.w += v.w;
        }
        reinterpret_cast<float4*>(g_fsum)[idx] = s;
    } else {
        int idx = (blockIdx.x - 1024) * 256 + threadIdx.x;   // < 294912
        int u = idx / KPAD;
        int k = idx - u * KPAD;
        int c = k >> 6;
        int kc = k & 63;
        int s = kc >> 4;
        int m16 = kc & 15;
        int w = m16 >> 1, h = m16 & 1;
        int pair = (w >> 1) + ((w & 1) << 2);
        int gi = c * 8 + s * 2 + (pair >= 4 ? 1 : 0);
        int off = ((pair & 3) << 1) + h;
        unsigned grp = grp_of(gi);
        int i = grp >> 8;
        int j = (int)(grp & 255) + off;
        float v = 0.f;
        if (j < 64) {
            v = W[u * 4096 + i * 64 + j];
            if (i != j) v += W[u * 4096 + j * 64 + i];
        }
        g_T[idx] = __float2half_rn(v);
    }
}

// ---------------- main GEMM: warp-specialized, fp16 m16n8k16 ----------------
// C[128b x 128u] += A[128 x 64k] * B[64k x 128], 36 chunks over padded K=2304.
// Warps 0-15: consumers = 8 tile-warps (4m x 2n, 32x64) x 2 k-split (2 ksteps each).
// Warps 16-19: producers - row-blocked A-gen (fp32 mul -> f16x2 pack) + cp.async B.
__global__ void __launch_bounds__(THREADS, 1)
quad_kernel(float* __restrict__ out) {
    extern __shared__ float sm[];
    float*    sF  = sm;
    unsigned* smw = reinterpret_cast<unsigned*>(sm);
    unsigned* sG  = smw + OFF_G;

    const int tid  = threadIdx.x;
    const int lane = tid & 31;
    const int warp = tid >> 5;
    const int b0 = blockIdx.x * BTILE;

    // ---- cooperative staging of sF (stride 65, +16 zero pad) and sG ----
    for (int idx = tid; idx < 2048; idx += THREADS) {
        int row = idx >> 4, c4 = (idx & 15) << 2;
        float4 v = *reinterpret_cast<const float4*>(
            g_fsum + (size_t)(b0 + row) * E_DIM + c4);
        sF[row * FSTR + c4 + 0] = v.x;
        sF[row * FSTR + c4 + 1] = v.y;
        sF[row * FSTR + c4 + 2] = v.z;
        sF[row * FSTR + c4 + 3] = v.w;
    }
    if (tid < 16) sF[128 * FSTR + tid] = 0.f;   // pad: last row may read j up to 70
    if (tid < NGRP) sG[tid] = grp_of(tid);
    __syncthreads();

    if (warp >= 16) {
        // ================= PRODUCER (128 threads) =================
        const int p = tid - 512;               // 0..127 (A row)
        const float* fr = sF + p * FSTR;
        const uint32_t sB0_u = smem_u32(smw + OFF_B0);
        const uint32_t sB1_u = smem_u32(smw + OFF_B1);
        const __half* gTh = g_T;

#pragma unroll 1
        for (int c = 0; c < NCHUNK; ++c) {
            const int s = c & 1;
            if (c >= 2) bar_sync(s ? EMPTY1 : EMPTY0, THREADS);

            // cp.async B(c): 16 KB = 1024 x 16B, 8 per thread, coalesced
            {
                uint32_t dstb = s ? sB1_u : sB0_u;
#pragma unroll
                for (int t = 0; t < 8; ++t) {
                    int idx = p + t * 128;           // 16B-chunk index
                    int row = idx >> 3, q = idx & 7;
                    cp16(dstb + (uint32_t)(row * RSTR + q * 4) * 4u,
                         gTh + (size_t)row * KPAD + c * 64 + q * 8);
                }
                cp_commit();
            }
            // gen A(c): row p; per 16k-step, two 8-groups X/Y, interleaved words
            {
                unsigned* dst = smw + (s ? OFF_A1 : OFF_A0) + p * RSTR;
#pragma unroll
                for (int st = 0; st < 4; ++st) {
                    unsigned gX = sG[c * 8 + st * 2];
                    unsigned gY = sG[c * 8 + st * 2 + 1];
                    const float fiX = fr[gX >> 8];
                    const float fiY = fr[gY >> 8];
                    const float* fjX = fr + (gX & 255);
                    const float* fjY = fr + (gY & 255);
                    __half2 w[8];
                    w[0] = __floats2half2_rn(fiX * fjX[0], fiX * fjX[1]);
                    w[1] = __floats2half2_rn(fiY * fjY[0], fiY * fjY[1]);
                    w[2] = __floats2half2_rn(fiX * fjX[2], fiX * fjX[3]);
                    w[3] = __floats2half2_rn(fiY * fjY[2], fiY * fjY[3]);
                    w[4] = __floats2half2_rn(fiX * fjX[4], fiX * fjX[5]);
                    w[5] = __floats2half2_rn(fiY * fjY[4], fiY * fjY[5]);
                    w[6] = __floats2half2_rn(fiX * fjX[6], fiX * fjX[7]);
                    w[7] = __floats2half2_rn(fiY * fjY[6], fiY * fjY[7]);
                    *reinterpret_cast<uint4*>(dst + st * 8)     = *reinterpret_cast<uint4*>(w);
                    *reinterpret_cast<uint4*>(dst + st * 8 + 4) = *reinterpret_cast<uint4*>(w + 4);
                }
            }
            cp_wait0();
            bar_arrive(s ? FULL1 : FULL0, THREADS);
        }
    } else {
        // ================= CONSUMER (512 threads, 16 warps) =================
        const int l4 = lane >> 2, k4 = lane & 3;
        const int twarp = warp & 7;
        const int kw    = warp >> 3;              // k-split half (2 ksteps each)
        const int row_base = (twarp & 3) * 32;    // 4-way m split
        const int col_base = (twarp >> 2) * 64;   // 2-way n split

        float acc[2][8][4];
#pragma unroll
        for (int mt = 0; mt < 2; ++mt)
#pragma unroll
            for (int nt = 0; nt < 8; ++nt)
#pragma unroll
                for (int x = 0; x < 4; ++x) acc[mt][nt][x] = 0.f;

#pragma unroll 1
        for (int c = 0; c < NCHUNK; ++c) {
            const int s = c & 1;
            bar_sync(s ? FULL1 : FULL0, THREADS);

            const unsigned* A = smw + (s ? OFF_A1 : OFF_A0);
            const unsigned* B = smw + (s ? OFF_B1 : OFF_B0);
#pragma unroll
            for (int sx = 0; sx < 2; ++sx) {
                const int st = kw * 2 + sx;
                const int kwrd = st * 8 + k4 * 2;
                uint2 aw[2][2];
#pragma unroll
                for (int mt = 0; mt < 2; ++mt) {
                    const unsigned* ap = A + (row_base + mt * 16 + l4) * RSTR + kwrd;
                    aw[mt][0] = *reinterpret_cast<const uint2*>(ap);
                    aw[mt][1] = *reinterpret_cast<const uint2*>(ap + 8 * RSTR);
                }
#pragma unroll
                for (int nt = 0; nt < 8; ++nt) {
                    uint2 bb = *reinterpret_cast<const uint2*>(
                        B + (col_base + nt * 8 + l4) * RSTR + kwrd);
#pragma unroll
                    for (int mt = 0; mt < 2; ++mt)
                        mma16(acc[mt][nt],
                              aw[mt][0].x, aw[mt][1].x, aw[mt][0].y, aw[mt][1].y,
                              bb.x, bb.y);
                }
            }
            bar_arrive(s ? EMPTY1 : EMPTY0, THREADS);
        }

        // ---- epilogue: sum k-split partials via smem, then STG ----
        bar_sync(CONS, 512);
        float4* sRed = reinterpret_cast<float4*>(sm + OFF_A0);   // 16*256 float4
        if (kw == 1) {
            const int idx = tid - 256;
#pragma unroll
            for (int mt = 0; mt < 2; ++mt)
#pragma unroll
                for (int nt = 0; nt < 8; ++nt) {
                    int q = mt * 8 + nt;
                    sRed[q * 256 + idx] = make_float4(acc[mt][nt][0], acc[mt][nt][1],
                                                      acc[mt][nt][2], acc[mt][nt][3]);
                }
        }
        bar_sync(CONS, 512);
        if (kw == 0) {
#pragma unroll
            for (int mt = 0; mt < 2; ++mt) {
#pragma unroll
                for (int nt = 0; nt < 8; ++nt) {
                    int q = mt * 8 + nt;
                    float4 p = sRed[q * 256 + tid];
                    float2 v0 = make_float2(acc[mt][nt][0] + p.x, acc[mt][nt][1] + p.y);
                    float2 v1 = make_float2(acc[mt][nt][2] + p.z, acc[mt][nt][3] + p.w);
                    const int rr = b0 + row_base + mt * 16 + l4;
                    const int cc = col_base + nt * 8 + k4 * 2;
                    *reinterpret_cast<float2*>(out + (size_t)rr * U_DIM + cc) = v0;
                    *reinterpret_cast<float2*>(out + (size_t)(rr + 8) * U_DIM + cc) = v1;
                }
            }
        }
    }
}

extern "C" void kernel_launch(void* const* d_in, const int* in_sizes, int n_in,
                              void* d_out, int out_size) {
    const float* embeds = (const float*)d_in[0];   // (16384, 39, 64)
    const float* W      = (const float*)d_in[1];   // (128, 64, 64)
    float* out          = (float*)d_out;           // (16384, 128)

    static int smem_set = 0;
    if (!smem_set) {
        cudaFuncSetAttribute(quad_kernel,
                             cudaFuncAttributeMaxDynamicSharedMemorySize, SMEM_BYTES);
        smem_set = 1;
    }

    prep_kernel<<<1024 + (U_DIM * KPAD) / 256, 256>>>(embeds, W);
    quad_kernel<<<B_TOTAL / BTILE, THREADS, SMEM_BYTES>>>(out);
}

// round 15
// speedup vs baseline: 1.5022x; 1.0259x over previous
#include <cuda_runtime.h>
#include <cuda_fp16.h>
#include <cstdint>

#define B_TOTAL 16384
#define F_FIELDS 39
#define E_DIM 64
#define U_DIM 128
#define BTILE 128
#define THREADS 640          // 16 consumer warps (8 tiles x 2 ksplit) + 4 producers
#define NGRP  288
#define KPAD  2304           // NGRP*8 = 18 chunks * 128
#define NCHUNK 18
#define FSTR 65
#define RSTR 72              // row stride in b32 words (64 data + 8 pad); 36 mod 16 = 4 -> conflict-free
// smem word(=float) offsets
#define OFF_A0 8336          // sF = 128*65 + 16 pad
#define OFF_A1 17552
#define OFF_B0 26768
#define OFF_B1 35984
#define OFF_G  45200
#define SMEM_FLOATS 45488
#define SMEM_BYTES  (SMEM_FLOATS * 4)   // 181952 B, 1 CTA/SM

// named barrier ids (0 reserved for __syncthreads)
#define FULL0 1
#define FULL1 2
#define EMPTY0 3
#define EMPTY1 4
#define CONS   5

__device__ float  g_fsum[B_TOTAL * E_DIM];
__device__ __half g_T[U_DIM * KPAD];   // rn(fp16) packed symmetric W, perm layout

__device__ __forceinline__ uint32_t smem_u32(const void* p) {
    uint32_t a;
    asm("{ .reg .u64 t; cvta.to.shared.u64 t, %1; cvt.u32.u64 %0, t; }" : "=r"(a) : "l"(p));
    return a;
}
__device__ __forceinline__ void cp16(uint32_t dst, const void* src) {
    asm volatile("cp.async.cg.shared.global [%0], [%1], 16;" :: "r"(dst), "l"(src) : "memory");
}
__device__ __forceinline__ void cp_commit() {
    asm volatile("cp.async.commit_group;" ::: "memory");
}
__device__ __forceinline__ void cp_wait0() {
    asm volatile("cp.async.wait_group 0;" ::: "memory");
}
__device__ __forceinline__ void bar_sync(int id, int cnt) {
    asm volatile("bar.sync %0, %1;" :: "r"(id), "r"(cnt) : "memory");
}
__device__ __forceinline__ void bar_arrive(int id, int cnt) {
    asm volatile("bar.arrive %0, %1;" :: "r"(id), "r"(cnt) : "memory");
}
// fp16 mma: D(16x8,f32) += A(16x16,f16) * B(16x8,f16)
__device__ __forceinline__ void mma16(float* c, unsigned a0, unsigned a1,
                                      unsigned a2, unsigned a3,
                                      unsigned b0, unsigned b1) {
    asm volatile(
        "mma.sync.aligned.m16n8k16.row.col.f32.f16.f16.f32 "
        "{%0,%1,%2,%3}, {%4,%5,%6,%7}, {%8,%9}, {%0,%1,%2,%3};"
        : "+f"(c[0]), "+f"(c[1]), "+f"(c[2]), "+f"(c[3])
        : "r"(a0), "r"(a1), "r"(a2), "r"(a3), "r"(b0), "r"(b1));
}

// group g -> (i<<8)|j0 : row-blocked upper-tri, rows padded to 8. 288 groups.
// cum(x) = 8*(8x - x(x-1)/2) -> {0,64,120,168,208,240,264,280}. Absolute-prefix compare.
__device__ __forceinline__ unsigned grp_of(int g) {
    int b = 0;
#pragma unroll
    for (int x = 1; x <= 7; ++x) {
        int cumx = 8 * (8 * x - ((x * (x - 1)) >> 1));
        if (g >= cumx) b = x;
    }
    int cum = 8 * (8 * b - ((b * (b - 1)) >> 1));
    int idx = g - cum;
    int ng = 8 - b;
    int ro = idx / ng;
    int jg = idx - ro * ng;
    int r = 8 * b + ro;
    return ((unsigned)r << 8) | (unsigned)(r + 8 * jg);
}

// ---------------- fused prep: feat_sum + packed symmetric T (fp16, perm layout) ----
// k_mem decode: chunk c=k/128 (16 groups), kstep s=(k%128)/16, word w=(k%16)/2, h=k&1;
// logical pair = w/2 + (w&1)*4; group = c*16 + s*2 + (pair>=4); off = (pair&3)*2+h.
__global__ void prep_kernel(const float* __restrict__ embeds,
                            const float* __restrict__ W) {
    if (blockIdx.x < 1024) {
        int idx = blockIdx.x * 256 + threadIdx.x;
        int b = idx >> 4;
        int e4 = idx & 15;
        const float4* p = reinterpret_cast<const float4*>(embeds)
                          + (size_t)b * (F_FIELDS * E_DIM / 4) + e4;
        float4 s = make_float4(0.f, 0.f, 0.f, 0.f);
#pragma unroll
        for (int f = 0; f < F_FIELDS; ++f) {
            float4 v = p[f * (E_DIM / 4)];
            s.x += v.x; s.y += v.y; s.z += v.z; s.w += v.w;
        }
        reinterpret_cast<float4*>(g_fsum)[idx] = s;
    } else {
        int idx = (blockIdx.x - 1024) * 256 + threadIdx.x;   // < 294912
        int u = idx / KPAD;
        int k = idx - u * KPAD;
        int c = k >> 7;
        int kc = k & 127;
        int s = kc >> 4;
        int m16 = kc & 15;
        int w = m16 >> 1, h = m16 & 1;
        int pair = (w >> 1) + ((w & 1) << 2);
        int gi = c * 16 + s * 2 + (pair >= 4 ? 1 : 0);
        int off = ((pair & 3) << 1) + h;
        unsigned grp = grp_of(gi);
        int i = grp >> 8;
        int j = (int)(grp & 255) + off;
        float v = 0.f;
        if (j < 64) {
            v = W[u * 4096 + i * 64 + j];
            if (i != j) v += W[u * 4096 + j * 64 + i];
        }
        g_T[idx] = __float2half_rn(v);
    }
}

// ---------------- main GEMM: warp-specialized, fp16 m16n8k16, KC=128 ----------------
// C[128b x 128u] += A[128 x 128k] * B[128k x 128], 18 chunks over padded K=2304.
// Warps 0-15: consumers = 8 tile-warps (4m x 2n, 32x64) x 2 k-split (4 ksteps each).
// Warps 16-19: producers - row-blocked A-gen (fp32 mul -> f16x2 pack) + cp.async B.
__global__ void __launch_bounds__(THREADS, 1)
quad_kernel(float* __restrict__ out) {
    extern __shared__ float sm[];
    float*    sF  = sm;
    unsigned* smw = reinterpret_cast<unsigned*>(sm);
    unsigned* sG  = smw + OFF_G;

    const int tid  = threadIdx.x;
    const int lane = tid & 31;
    const int warp = tid >> 5;
    const int b0 = blockIdx.x * BTILE;

    // ---- cooperative staging of sF (stride 65, +16 zero pad) and sG ----
    for (int idx = tid; idx < 2048; idx += THREADS) {
        int row = idx >> 4, c4 = (idx & 15) << 2;
        float4 v = *reinterpret_cast<const float4*>(
            g_fsum + (size_t)(b0 + row) * E_DIM + c4);
        sF[row * FSTR + c4 + 0] = v.x;
        sF[row * FSTR + c4 + 1] = v.y;
        sF[row * FSTR + c4 + 2] = v.z;
        sF[row * FSTR + c4 + 3] = v.w;
    }
    if (tid < 16) sF[128 * FSTR + tid] = 0.f;   // pad: last row may read j up to 70
    if (tid < NGRP) sG[tid] = grp_of(tid);
    __syncthreads();

    if (warp >= 16) {
        // ================= PRODUCER (128 threads) =================
        const int p = tid - 512;               // 0..127 (A row)
        const float* fr = sF + p * FSTR;
        const uint32_t sB0_u = smem_u32(smw + OFF_B0);
        const uint32_t sB1_u = smem_u32(smw + OFF_B1);
        const __half* gTh = g_T;

#pragma unroll 1
        for (int c = 0; c < NCHUNK; ++c) {
            const int s = c & 1;
            if (c >= 2) bar_sync(s ? EMPTY1 : EMPTY0, THREADS);

            // cp.async B(c): 32 KB = 2048 x 16B, 16 per thread, coalesced
            {
                uint32_t dstb = s ? sB1_u : sB0_u;
#pragma unroll
                for (int t = 0; t < 16; ++t) {
                    int idx = p + t * 128;           // 16B-chunk index
                    int row = idx >> 4, q = idx & 15;
                    cp16(dstb + (uint32_t)(row * RSTR + q * 4) * 4u,
                         gTh + (size_t)row * KPAD + c * 128 + q * 8);
                }
                cp_commit();
            }
            // gen A(c): row p; 8 ksteps, each two 8-groups X/Y, interleaved words
            {
                unsigned* dst = smw + (s ? OFF_A1 : OFF_A0) + p * RSTR;
#pragma unroll
                for (int st = 0; st < 8; ++st) {
                    unsigned gX = sG[c * 16 + st * 2];
                    unsigned gY = sG[c * 16 + st * 2 + 1];
                    const float fiX = fr[gX >> 8];
                    const float fiY = fr[gY >> 8];
                    const float* fjX = fr + (gX & 255);
                    const float* fjY = fr + (gY & 255);
                    __half2 w[8];
                    w[0] = __floats2half2_rn(fiX * fjX[0], fiX * fjX[1]);
                    w[1] = __floats2half2_rn(fiY * fjY[0], fiY * fjY[1]);
                    w[2] = __floats2half2_rn(fiX * fjX[2], fiX * fjX[3]);
                    w[3] = __floats2half2_rn(fiY * fjY[2], fiY * fjY[3]);
                    w[4] = __floats2half2_rn(fiX * fjX[4], fiX * fjX[5]);
                    w[5] = __floats2half2_rn(fiY * fjY[4], fiY * fjY[5]);
                    w[6] = __floats2half2_rn(fiX * fjX[6], fiX * fjX[7]);
                    w[7] = __floats2half2_rn(fiY * fjY[6], fiY * fjY[7]);
                    *reinterpret_cast<uint4*>(dst + st * 8)     = *reinterpret_cast<uint4*>(w);
                    *reinterpret_cast<uint4*>(dst + st * 8 + 4) = *reinterpret_cast<uint4*>(w + 4);
                }
            }
            cp_wait0();
            bar_arrive(s ? FULL1 : FULL0, THREADS);
        }
    } else {
        // ================= CONSUMER (512 threads, 16 warps) =================
        const int l4 = lane >> 2, k4 = lane & 3;
        const int twarp = warp & 7;
        const int kw    = warp >> 3;              // k-split half (4 ksteps each)
        const int row_base = (twarp & 3) * 32;    // 4-way m split
        const int col_base = (twarp >> 2) * 64;   // 2-way n split

        float acc[2][8][4];
#pragma unroll
        for (int mt = 0; mt < 2; ++mt)
#pragma unroll
            for (int nt = 0; nt < 8; ++nt)
#pragma unroll
                for (int x = 0; x < 4; ++x) acc[mt][nt][x] = 0.f;

#pragma unroll 1
        for (int c = 0; c < NCHUNK; ++c) {
            const int s = c & 1;
            bar_sync(s ? FULL1 : FULL0, THREADS);

            const unsigned* A = smw + (s ? OFF_A1 : OFF_A0);
            const unsigned* B = smw + (s ? OFF_B1 : OFF_B0);
#pragma unroll
            for (int sx = 0; sx < 4; ++sx) {
                const int st = kw * 4 + sx;
                const int kwrd = st * 8 + k4 * 2;
                uint2 aw[2][2];
#pragma unroll
                for (int mt = 0; mt < 2; ++mt) {
                    const unsigned* ap = A + (row_base + mt * 16 + l4) * RSTR + kwrd;
                    aw[mt][0] = *reinterpret_cast<const uint2*>(ap);
                    aw[mt][1] = *reinterpret_cast<const uint2*>(ap + 8 * RSTR);
                }
#pragma unroll
                for (int nt = 0; nt < 8; ++nt) {
                    uint2 bb = *reinterpret_cast<const uint2*>(
                        B + (col_base + nt * 8 + l4) * RSTR + kwrd);
#pragma unroll
                    for (int mt = 0; mt < 2; ++mt)
                        mma16(acc[mt][nt],
                              aw[mt][0].x, aw[mt][1].x, aw[mt][0].y, aw[mt][1].y,
                              bb.x, bb.y);
                }
            }
            bar_arrive(s ? EMPTY1 : EMPTY0, THREADS);
        }

        // ---- epilogue: sum k-split partials via smem, then STG ----
        bar_sync(CONS, 512);
        float4* sRed = reinterpret_cast<float4*>(sm + OFF_A0);   // 16*256 float4
        if (kw == 1) {
            const int idx = tid - 256;
#pragma unroll
            for (int mt = 0; mt < 2; ++mt)
#pragma unroll
                for (int nt = 0; nt < 8; ++nt) {
                    int q = mt * 8 + nt;
                    sRed[q * 256 + idx] = make_float4(acc[mt][nt][0], acc[mt][nt][1],
                                                      acc[mt][nt][2], acc[mt][nt][3]);
                }
        }
        bar_sync(CONS, 512);
        if (kw == 0) {
#pragma unroll
            for (int mt = 0; mt < 2; ++mt) {
#pragma unroll
                for (int nt = 0; nt < 8; ++nt) {
                    int q = mt * 8 + nt;
                    float4 p = sRed[q * 256 + tid];
                    float2 v0 = make_float2(acc[mt][nt][0] + p.x, acc[mt][nt][1] + p.y);
                    float2 v1 = make_float2(acc[mt][nt][2] + p.z, acc[mt][nt][3] + p.w);
                    const int rr = b0 + row_base + mt * 16 + l4;
                    const int cc = col_base + nt * 8 + k4 * 2;
                    *reinterpret_cast<float2*>(out + (size_t)rr * U_DIM + cc) = v0;
                    *reinterpret_cast<float2*>(out + (size_t)(rr + 8) * U_DIM + cc) = v1;
                }
            }
        }
    }
}

extern "C" void kernel_launch(void* const* d_in, const int* in_sizes, int n_in,
                              void* d_out, int out_size) {
    const float* embeds = (const float*)d_in[0];   // (16384, 39, 64)
    const float* W      = (const float*)d_in[1];   // (128, 64, 64)
    float* out          = (float*)d_out;           // (16384, 128)

    static int smem_set = 0;
    if (!smem_set) {
        cudaFuncSetAttribute(quad_kernel,
                             cudaFuncAttributeMaxDynamicSharedMemorySize, SMEM_BYTES);
        smem_set = 1;
    }

    prep_kernel<<<1024 + (U_DIM * KPAD) / 256, 256>>>(embeds, W);
    quad_kernel<<<B_TOTAL / BTILE, THREADS, SMEM_BYTES>>>(out);
}

// round 16
// speedup vs baseline: 1.5450x; 1.0284x over previous
#include <cuda_runtime.h>
#include <cuda_fp16.h>
#include <cstdint>

#define B_TOTAL 16384
#define F_FIELDS 39
#define E_DIM 64
#define U_DIM 128
#define BTILE 128
#define THREADS 640          // 16 consumer warps (8 tiles x 2 ksplit) + 4 producers
#define NGRP  288
#define KPAD  2304           // NGRP*8 = 18 chunks * 128
#define NCHUNK 18
#define FSTR 65
#define RSTR 68              // row stride in b32 words (64 data + 4 pad); 272B % 128 = 16 -> LDSM conflict-free
// smem word(=float) offsets
#define OFF_A0 8336          // sF = 128*65 + 16 pad (zeroed from word 8319)
#define OFF_A1 17040
#define OFF_B0 25744
#define OFF_B1 34448
#define OFF_G  43152
#define SMEM_FLOATS 43440
#define SMEM_BYTES  (SMEM_FLOATS * 4)   // 173760 B, 1 CTA/SM

// named barrier ids (0 reserved for __syncthreads)
#define FULL0 1
#define FULL1 2
#define EMPTY0 3
#define EMPTY1 4
#define CONS   5

__device__ float  g_fsum[B_TOTAL * E_DIM];
__device__ __half g_T[U_DIM * KPAD];   // rn(fp16) packed symmetric W, NATURAL k layout

__device__ __forceinline__ uint32_t smem_u32(const void* p) {
    uint32_t a;
    asm("{ .reg .u64 t; cvta.to.shared.u64 t, %1; cvt.u32.u64 %0, t; }" : "=r"(a) : "l"(p));
    return a;
}
__device__ __forceinline__ void cp16(uint32_t dst, const void* src) {
    asm volatile("cp.async.cg.shared.global [%0], [%1], 16;" :: "r"(dst), "l"(src) : "memory");
}
__device__ __forceinline__ void cp_commit() {
    asm volatile("cp.async.commit_group;" ::: "memory");
}
__device__ __forceinline__ void cp_wait0() {
    asm volatile("cp.async.wait_group 0;" ::: "memory");
}
__device__ __forceinline__ void bar_sync(int id, int cnt) {
    asm volatile("bar.sync %0, %1;" :: "r"(id), "r"(cnt) : "memory");
}
__device__ __forceinline__ void bar_arrive(int id, int cnt) {
    asm volatile("bar.arrive %0, %1;" :: "r"(id), "r"(cnt) : "memory");
}
__device__ __forceinline__ void ldsm4(unsigned* d, uint32_t addr) {
    asm volatile("ldmatrix.sync.aligned.m8n8.x4.shared.b16 {%0,%1,%2,%3}, [%4];"
        : "=r"(d[0]), "=r"(d[1]), "=r"(d[2]), "=r"(d[3]) : "r"(addr));
}
// fp16 mma: D(16x8,f32) += A(16x16,f16) * B(16x8,f16)
__device__ __forceinline__ void mma16(float* c, unsigned a0, unsigned a1,
                                      unsigned a2, unsigned a3,
                                      unsigned b0, unsigned b1) {
    asm volatile(
        "mma.sync.aligned.m16n8k16.row.col.f32.f16.f16.f32 "
        "{%0,%1,%2,%3}, {%4,%5,%6,%7}, {%8,%9}, {%0,%1,%2,%3};"
        : "+f"(c[0]), "+f"(c[1]), "+f"(c[2]), "+f"(c[3])
        : "r"(a0), "r"(a1), "r"(a2), "r"(a3), "r"(b0), "r"(b1));
}

// group g -> (i<<8)|j0 : row-blocked upper-tri, rows padded to 8. 288 groups.
// cum(x) = 8*(8x - x(x-1)/2) -> {0,64,120,168,208,240,264,280}. Absolute-prefix compare.
__device__ __forceinline__ unsigned grp_of(int g) {
    int b = 0;
#pragma unroll
    for (int x = 1; x <= 7; ++x) {
        int cumx = 8 * (8 * x - ((x * (x - 1)) >> 1));
        if (g >= cumx) b = x;
    }
    int cum = 8 * (8 * b - ((b * (b - 1)) >> 1));
    int idx = g - cum;
    int ng = 8 - b;
    int ro = idx / ng;
    int jg = idx - ro * ng;
    int r = 8 * b + ro;
    return ((unsigned)r << 8) | (unsigned)(r + 8 * jg);
}

// ---------------- fused prep: feat_sum + packed symmetric T (fp16, natural layout) ----
__global__ void prep_kernel(const float* __restrict__ embeds,
                            const float* __restrict__ W) {
    if (blockIdx.x < 1024) {
        int idx = blockIdx.x * 256 + threadIdx.x;
        int b = idx >> 4;
        int e4 = idx & 15;
        const float4* p = reinterpret_cast<const float4*>(embeds)
                          + (size_t)b * (F_FIELDS * E_DIM / 4) + e4;
        float4 s = make_float4(0.f, 0.f, 0.f, 0.f);
#pragma unroll
        for (int f = 0; f < F_FIELDS; ++f) {
            float4 v = p[f * (E_DIM / 4)];
            s.x += v.x; s.y += v.y; s.z += v.z; s.w += v.w;
        }
        reinterpret_cast<float4*>(g_fsum)[idx] = s;
    } else {
        int idx = (blockIdx.x - 1024) * 256 + threadIdx.x;   // < 294912
        int u = idx / KPAD;
        int k = idx - u * KPAD;
        unsigned grp = grp_of(k >> 3);
        int i = grp >> 8;
        int j = (int)(grp & 255) + (k & 7);
        float v = 0.f;
        if (j < 64) {
            v = W[u * 4096 + i * 64 + j];
            if (i != j) v += W[u * 4096 + j * 64 + i];
        }
        g_T[idx] = __float2half_rn(v);
    }
}

// ---------------- main GEMM: warp-specialized, fp16 m16n8k16 + ldmatrix ----------------
// C[128b x 128u] += A[128 x 128k] * B[128k x 128], 18 chunks over padded K=2304.
// Warps 0-15: consumers = 8 tile-warps (4m x 2n, 32x64) x 2 k-split (4 ksteps each);
//             fragments via ldmatrix.x4 (A non-trans; B = A-style on [u][k] tile).
// Warps 16-19: producers - row-blocked A-gen (natural f16x2 pairs) + cp.async B.
__global__ void __launch_bounds__(THREADS, 1)
quad_kernel(float* __restrict__ out) {
    extern __shared__ float sm[];
    float*    sF  = sm;
    unsigned* smw = reinterpret_cast<unsigned*>(sm);
    unsigned* sG  = smw + OFF_G;

    const int tid  = threadIdx.x;
    const int lane = tid & 31;
    const int warp = tid >> 5;
    const int b0 = blockIdx.x * BTILE;

    // ---- cooperative staging of sF (stride 65) and sG; zero tail pad ----
    for (int idx = tid; idx < 2048; idx += THREADS) {
        int row = idx >> 4, c4 = (idx & 15) << 2;
        float4 v = *reinterpret_cast<const float4*>(
            g_fsum + (size_t)(b0 + row) * E_DIM + c4);
        sF[row * FSTR + c4 + 0] = v.x;
        sF[row * FSTR + c4 + 1] = v.y;
        sF[row * FSTR + c4 + 2] = v.z;
        sF[row * FSTR + c4 + 3] = v.w;
    }
    if (tid < 17) sF[8319 + tid] = 0.f;   // row 127 A-gen may read j up to 70
    if (tid < NGRP) sG[tid] = grp_of(tid);
    __syncthreads();

    if (warp >= 16) {
        // ================= PRODUCER (128 threads) =================
        const int p = tid - 512;               // 0..127 (A row)
        const float* fr = sF + p * FSTR;
        const uint32_t sB0_u = smem_u32(smw + OFF_B0);
        const uint32_t sB1_u = smem_u32(smw + OFF_B1);
        const __half* gTh = g_T;

#pragma unroll 1
        for (int c = 0; c < NCHUNK; ++c) {
            const int s = c & 1;
            if (c >= 2) bar_sync(s ? EMPTY1 : EMPTY0, THREADS);

            // cp.async B(c): 32 KB = 2048 x 16B, 16 per thread, coalesced
            {
                uint32_t dstb = s ? sB1_u : sB0_u;
#pragma unroll
                for (int t = 0; t < 16; ++t) {
                    int idx = p + t * 128;           // 16B-chunk index
                    int row = idx >> 4, q = idx & 15;
                    cp16(dstb + (uint32_t)(row * RSTR + q * 4) * 4u,
                         gTh + (size_t)row * KPAD + c * 128 + q * 8);
                }
                cp_commit();
            }
            // gen A(c): row p; 8 ksteps, each two 8-groups X (k0-7) then Y (k8-15)
            {
                unsigned* dst = smw + (s ? OFF_A1 : OFF_A0) + p * RSTR;
#pragma unroll
                for (int st = 0; st < 8; ++st) {
                    unsigned gX = sG[c * 16 + st * 2];
                    unsigned gY = sG[c * 16 + st * 2 + 1];
                    const float fiX = fr[gX >> 8];
                    const float fiY = fr[gY >> 8];
                    const float* fjX = fr + (gX & 255);
                    const float* fjY = fr + (gY & 255);
                    __half2 w[8];
                    w[0] = __floats2half2_rn(fiX * fjX[0], fiX * fjX[1]);
                    w[1] = __floats2half2_rn(fiX * fjX[2], fiX * fjX[3]);
                    w[2] = __floats2half2_rn(fiX * fjX[4], fiX * fjX[5]);
                    w[3] = __floats2half2_rn(fiX * fjX[6], fiX * fjX[7]);
                    w[4] = __floats2half2_rn(fiY * fjY[0], fiY * fjY[1]);
                    w[5] = __floats2half2_rn(fiY * fjY[2], fiY * fjY[3]);
                    w[6] = __floats2half2_rn(fiY * fjY[4], fiY * fjY[5]);
                    w[7] = __floats2half2_rn(fiY * fjY[6], fiY * fjY[7]);
                    *reinterpret_cast<uint4*>(dst + st * 8)     = *reinterpret_cast<uint4*>(w);
                    *reinterpret_cast<uint4*>(dst + st * 8 + 4) = *reinterpret_cast<uint4*>(w + 4);
                }
            }
            cp_wait0();
            bar_arrive(s ? FULL1 : FULL0, THREADS);
        }
    } else {
        // ================= CONSUMER (512 threads, 16 warps) =================
        const int l4 = lane >> 2, k4 = lane & 3;
        const int twarp = warp & 7;
        const int kw    = warp >> 3;              // k-split half (4 ksteps each)
        const int row_base = (twarp & 3) * 32;    // 4-way m split
        const int col_base = (twarp >> 2) * 64;   // 2-way n split

        // ldmatrix lane addressing: row = base + (lane&15), byte += (lane>>4)*16
        const int rsel = lane & 15;
        const int bsel = (lane >> 4) * 16;
        uint32_t aAddr[2][2], bAddr[2][4];
#pragma unroll
        for (int s = 0; s < 2; ++s) {
            uint32_t as = smem_u32(smw + (s ? OFF_A1 : OFF_A0));
            uint32_t bs = smem_u32(smw + (s ? OFF_B1 : OFF_B0));
#pragma unroll
            for (int mt = 0; mt < 2; ++mt)
                aAddr[s][mt] = as + (uint32_t)((row_base + mt * 16 + rsel) * RSTR) * 4u + bsel;
#pragma unroll
            for (int bt = 0; bt < 4; ++bt)
                bAddr[s][bt] = bs + (uint32_t)((col_base + bt * 16 + rsel) * RSTR) * 4u + bsel;
        }

        float acc[2][8][4];
#pragma unroll
        for (int mt = 0; mt < 2; ++mt)
#pragma unroll
            for (int nt = 0; nt < 8; ++nt)
#pragma unroll
                for (int x = 0; x < 4; ++x) acc[mt][nt][x] = 0.f;

#pragma unroll 1
        for (int c = 0; c < NCHUNK; ++c) {
            const int s = c & 1;
            bar_sync(s ? FULL1 : FULL0, THREADS);
#pragma unroll
            for (int sx = 0; sx < 4; ++sx) {
                const uint32_t koff = (uint32_t)(kw * 4 + sx) * 32u;
                unsigned af0[4], af1[4];
                ldsm4(af0, aAddr[s][0] + koff);
                ldsm4(af1, aAddr[s][1] + koff);
#pragma unroll
                for (int bt = 0; bt < 4; ++bt) {
                    unsigned bf[4];
                    ldsm4(bf, bAddr[s][bt] + koff);
                    const int nt0 = bt * 2, nt1 = bt * 2 + 1;
                    mma16(acc[0][nt0], af0[0], af0[1], af0[2], af0[3], bf[0], bf[2]);
                    mma16(acc[1][nt0], af1[0], af1[1], af1[2], af1[3], bf[0], bf[2]);
                    mma16(acc[0][nt1], af0[0], af0[1], af0[2], af0[3], bf[1], bf[3]);
                    mma16(acc[1][nt1], af1[0], af1[1], af1[2], af1[3], bf[1], bf[3]);
                }
            }
            bar_arrive(s ? EMPTY1 : EMPTY0, THREADS);
        }

        // ---- epilogue: sum k-split partials via smem, then STG ----
        bar_sync(CONS, 512);
        float4* sRed = reinterpret_cast<float4*>(sm + OFF_A0);   // 16*256 float4
        if (kw == 1) {
            const int idx = tid - 256;
#pragma unroll
            for (int mt = 0; mt < 2; ++mt)
#pragma unroll
                for (int nt = 0; nt < 8; ++nt) {
                    int q = mt * 8 + nt;
                    sRed[q * 256 + idx] = make_float4(acc[mt][nt][0], acc[mt][nt][1],
                                                      acc[mt][nt][2], acc[mt][nt][3]);
                }
        }
        bar_sync(CONS, 512);
        if (kw == 0) {
#pragma unroll
            for (int mt = 0; mt < 2; ++mt) {
#pragma unroll
                for (int nt = 0; nt < 8; ++nt) {
                    int q = mt * 8 + nt;
                    float4 p = sRed[q * 256 + tid];
                    float2 v0 = make_float2(acc[mt][nt][0] + p.x, acc[mt][nt][1] + p.y);
                    float2 v1 = make_float2(acc[mt][nt][2] + p.z, acc[mt][nt][3] + p.w);
                    const int rr = b0 + row_base + mt * 16 + l4;
                    const int cc = col_base + nt * 8 + k4 * 2;
                    *reinterpret_cast<float2*>(out + (size_t)rr * U_DIM + cc) = v0;
                    *reinterpret_cast<float2*>(out + (size_t)(rr + 8) * U_DIM + cc) = v1;
                }
            }
        }
    }
}

extern "C" void kernel_launch(void* const* d_in, const int* in_sizes, int n_in,
                              void* d_out, int out_size) {
    const float* embeds = (const float*)d_in[0];   // (16384, 39, 64)
    const float* W      = (const float*)d_in[1];   // (128, 64, 64)
    float* out          = (float*)d_out;           // (16384, 128)

    static int smem_set = 0;
    if (!smem_set) {
        cudaFuncSetAttribute(quad_kernel,
                             cudaFuncAttributeMaxDynamicSharedMemorySize, SMEM_BYTES);
        smem_set = 1;
    }

    prep_kernel<<<1024 + (U_DIM * KPAD) / 256, 256>>>(embeds, W);
    quad_kernel<<<B_TOTAL / BTILE, THREADS, SMEM_BYTES>>>(out);
}

// round 17
// speedup vs baseline: 1.5485x; 1.0023x over previous
#include <cuda_runtime.h>
#include <cuda_fp16.h>
#include <cstdint>

#define B_TOTAL 16384
#define F_FIELDS 39
#define E_DIM 64
#define U_DIM 128
#define BTILE 128
#define THREADS 640          // 16 consumer warps (8 tiles x 2 ksplit) + 4 producers
#define NGRP  288
#define KPAD  2304           // NGRP*8 = 18 chunks * 128
#define NCHUNK 18
#define FSTR 68              // 272 B row stride -> 16B-aligned rows for float4 fj reads
#define RSTR 68              // stage row stride in b32 words; 272B % 128 = 16 -> LDSM conflict-free
// smem word(=float) offsets
#define OFF_A0 8704          // sF = 128*68
#define OFF_A1 17408
#define OFF_B0 26112
#define OFF_B1 34816
#define OFF_G  43520
#define SMEM_FLOATS 43808
#define SMEM_BYTES  (SMEM_FLOATS * 4)   // 175232 B, 1 CTA/SM

// named barrier ids (0 reserved for __syncthreads)
#define FULL0 1
#define FULL1 2
#define EMPTY0 3
#define EMPTY1 4
#define CONS   5

__device__ float  g_fsum[B_TOTAL * E_DIM];
__device__ __half g_T[U_DIM * KPAD];   // rn(fp16) packed symmetric W; sub-diagonal slots zeroed

__device__ __forceinline__ uint32_t smem_u32(const void* p) {
    uint32_t a;
    asm("{ .reg .u64 t; cvta.to.shared.u64 t, %1; cvt.u32.u64 %0, t; }" : "=r"(a) : "l"(p));
    return a;
}
__device__ __forceinline__ void cp16(uint32_t dst, const void* src) {
    asm volatile("cp.async.cg.shared.global [%0], [%1], 16;" :: "r"(dst), "l"(src) : "memory");
}
__device__ __forceinline__ void cp_commit() {
    asm volatile("cp.async.commit_group;" ::: "memory");
}
__device__ __forceinline__ void cp_wait0() {
    asm volatile("cp.async.wait_group 0;" ::: "memory");
}
__device__ __forceinline__ void bar_sync(int id, int cnt) {
    asm volatile("bar.sync %0, %1;" :: "r"(id), "r"(cnt) : "memory");
}
__device__ __forceinline__ void bar_arrive(int id, int cnt) {
    asm volatile("bar.arrive %0, %1;" :: "r"(id), "r"(cnt) : "memory");
}
__device__ __forceinline__ void ldsm4(unsigned* d, uint32_t addr) {
    asm volatile("ldmatrix.sync.aligned.m8n8.x4.shared.b16 {%0,%1,%2,%3}, [%4];"
        : "=r"(d[0]), "=r"(d[1]), "=r"(d[2]), "=r"(d[3]) : "r"(addr));
}
// fp16 mma: D(16x8,f32) += A(16x16,f16) * B(16x8,f16)
__device__ __forceinline__ void mma16(float* c, unsigned a0, unsigned a1,
                                      unsigned a2, unsigned a3,
                                      unsigned b0, unsigned b1) {
    asm volatile(
        "mma.sync.aligned.m16n8k16.row.col.f32.f16.f16.f32 "
        "{%0,%1,%2,%3}, {%4,%5,%6,%7}, {%8,%9}, {%0,%1,%2,%3};"
        : "+f"(c[0]), "+f"(c[1]), "+f"(c[2]), "+f"(c[3])
        : "r"(a0), "r"(a1), "r"(a2), "r"(a3), "r"(b0), "r"(b1));
}

// group g -> (r<<8)|j0 : row-blocked, ALIGNED j-groups. Row r (block b=r/8) has
// groups a = b..7, j0 = 8a (16B-aligned). Count per row = 8-b, cum over blocks
// = {0,64,120,168,208,240,264,280}*? same prefix as before (8 rows x (8-b) groups).
__device__ __forceinline__ unsigned grp_of(int g) {
    int b = 0;
#pragma unroll
    for (int x = 1; x <= 7; ++x) {
        int cumx = 8 * (8 * x - ((x * (x - 1)) >> 1));
        if (g >= cumx) b = x;
    }
    int cum = 8 * (8 * b - ((b * (b - 1)) >> 1));
    int idx = g - cum;
    int ng = 8 - b;
    int ro = idx / ng;
    int jg = idx - ro * ng;
    int r = 8 * b + ro;
    int j0 = 8 * (b + jg);
    return ((unsigned)r << 8) | (unsigned)j0;
}

// ---------------- fused prep: feat_sum + packed symmetric T (fp16, aligned groups) ----
__global__ void prep_kernel(const float* __restrict__ embeds,
                            const float* __restrict__ W) {
    if (blockIdx.x < 1024) {
        int idx = blockIdx.x * 256 + threadIdx.x;
        int b = idx >> 4;
        int e4 = idx & 15;
        const float4* p = reinterpret_cast<const float4*>(embeds)
                          + (size_t)b * (F_FIELDS * E_DIM / 4) + e4;
        float4 s = make_float4(0.f, 0.f, 0.f, 0.f);
#pragma unroll
        for (int f = 0; f < F_FIELDS; ++f) {
            float4 v = p[f * (E_DIM / 4)];
            s.x += v.x; s.y += v.y; s.z += v.z; s.w += v.w;
        }
        reinterpret_cast<float4*>(g_fsum)[idx] = s;
    } else {
        int idx = (blockIdx.x - 1024) * 256 + threadIdx.x;   // < 294912
        int u = idx / KPAD;
        int k = idx - u * KPAD;
        unsigned grp = grp_of(k >> 3);
        int i = grp >> 8;
        int j = (int)(grp & 255) + (k & 7);    // j < 64 always
        float v = 0.f;
        if (j >= i) {                          // mask sub-diagonal slots to 0
            v = W[u * 4096 + i * 64 + j];
            if (i != j) v += W[u * 4096 + j * 64 + i];
        }
        g_T[idx] = __float2half_rn(v);
    }
}

// ---------------- main GEMM: warp-specialized, fp16 m16n8k16 + ldmatrix ----------------
// C[128b x 128u] += A[128 x 128k] * B[128k x 128], 18 chunks over padded K=2304.
// Warps 0-15: consumers = 8 tile-warps (4m x 2n, 32x64) x 2 k-split (4 ksteps each);
//             fragments via ldmatrix.x4, B-fragments register-pipelined across bt.
// Warps 16-19: producers - aligned-group A-gen (float4 fj) + cp.async B.
__global__ void __launch_bounds__(THREADS, 1)
quad_kernel(float* __restrict__ out) {
    extern __shared__ float sm[];
    float*    sF  = sm;
    unsigned* smw = reinterpret_cast<unsigned*>(sm);
    unsigned* sG  = smw + OFF_G;

    const int tid  = threadIdx.x;
    const int lane = tid & 31;
    const int warp = tid >> 5;
    const int b0 = blockIdx.x * BTILE;

    // ---- cooperative staging of sF (stride 68) and sG ----
    for (int idx = tid; idx < 2048; idx += THREADS) {
        int row = idx >> 4, c4 = (idx & 15) << 2;
        float4 v = *reinterpret_cast<const float4*>(
            g_fsum + (size_t)(b0 + row) * E_DIM + c4);
        *reinterpret_cast<float4*>(sF + row * FSTR + c4) = v;
    }
    if (tid < NGRP) sG[tid] = grp_of(tid);
    __syncthreads();

    if (warp >= 16) {
        // ================= PRODUCER (128 threads) =================
        const int p = tid - 512;               // 0..127 (A row)
        const float* fr = sF + p * FSTR;
        const uint32_t sB0_u = smem_u32(smw + OFF_B0);
        const uint32_t sB1_u = smem_u32(smw + OFF_B1);
        const __half* gTh = g_T;

#pragma unroll 1
        for (int c = 0; c < NCHUNK; ++c) {
            const int s = c & 1;
            if (c >= 2) bar_sync(s ? EMPTY1 : EMPTY0, THREADS);

            // cp.async B(c): 32 KB = 2048 x 16B, 16 per thread, coalesced
            {
                uint32_t dstb = s ? sB1_u : sB0_u;
#pragma unroll
                for (int t = 0; t < 16; ++t) {
                    int idx = p + t * 128;           // 16B-chunk index
                    int row = idx >> 4, q = idx & 15;
                    cp16(dstb + (uint32_t)(row * RSTR + q * 4) * 4u,
                         gTh + (size_t)row * KPAD + c * 128 + q * 8);
                }
                cp_commit();
            }
            // gen A(c): row p; 8 ksteps, each two aligned 8-groups X,Y (vector fj)
            {
                unsigned* dst = smw + (s ? OFF_A1 : OFF_A0) + p * RSTR;
#pragma unroll
                for (int st = 0; st < 8; ++st) {
                    unsigned gX = sG[c * 16 + st * 2];
                    unsigned gY = sG[c * 16 + st * 2 + 1];
                    const float fiX = fr[gX >> 8];
                    const float fiY = fr[gY >> 8];
                    const float4 xa = *reinterpret_cast<const float4*>(fr + (gX & 255));
                    const float4 xb = *reinterpret_cast<const float4*>(fr + (gX & 255) + 4);
                    const float4 ya = *reinterpret_cast<const float4*>(fr + (gY & 255));
                    const float4 yb = *reinterpret_cast<const float4*>(fr + (gY & 255) + 4);
                    __half2 w[8];
                    w[0] = __floats2half2_rn(fiX * xa.x, fiX * xa.y);
                    w[1] = __floats2half2_rn(fiX * xa.z, fiX * xa.w);
                    w[2] = __floats2half2_rn(fiX * xb.x, fiX * xb.y);
                    w[3] = __floats2half2_rn(fiX * xb.z, fiX * xb.w);
                    w[4] = __floats2half2_rn(fiY * ya.x, fiY * ya.y);
                    w[5] = __floats2half2_rn(fiY * ya.z, fiY * ya.w);
                    w[6] = __floats2half2_rn(fiY * yb.x, fiY * yb.y);
                    w[7] = __floats2half2_rn(fiY * yb.z, fiY * yb.w);
                    *reinterpret_cast<uint4*>(dst + st * 8)     = *reinterpret_cast<uint4*>(w);
                    *reinterpret_cast<uint4*>(dst + st * 8 + 4) = *reinterpret_cast<uint4*>(w + 4);
                }
            }
            cp_wait0();
            bar_arrive(s ? FULL1 : FULL0, THREADS);
        }
    } else {
        // ================= CONSUMER (512 threads, 16 warps) =================
        const int l4 = lane >> 2, k4 = lane & 3;
        const int twarp = warp & 7;
        const int kw    = warp >> 3;              // k-split half (4 ksteps each)
        const int row_base = (twarp & 3) * 32;    // 4-way m split
        const int col_base = (twarp >> 2) * 64;   // 2-way n split

        // ldmatrix lane addressing: row = base + (lane&15), byte += (lane>>4)*16
        const int rsel = lane & 15;
        const int bsel = (lane >> 4) * 16;
        uint32_t aAddr[2][2], bAddr[2][4];
#pragma unroll
        for (int s = 0; s < 2; ++s) {
            uint32_t as = smem_u32(smw + (s ? OFF_A1 : OFF_A0));
            uint32_t bs = smem_u32(smw + (s ? OFF_B1 : OFF_B0));
#pragma unroll
            for (int mt = 0; mt < 2; ++mt)
                aAddr[s][mt] = as + (uint32_t)((row_base + mt * 16 + rsel) * RSTR) * 4u + bsel;
#pragma unroll
            for (int bt = 0; bt < 4; ++bt)
                bAddr[s][bt] = bs + (uint32_t)((col_base + bt * 16 + rsel) * RSTR) * 4u + bsel;
        }

        float acc[2][8][4];
#pragma unroll
        for (int mt = 0; mt < 2; ++mt)
#pragma unroll
            for (int nt = 0; nt < 8; ++nt)
#pragma unroll
                for (int x = 0; x < 4; ++x) acc[mt][nt][x] = 0.f;

#pragma unroll 1
        for (int c = 0; c < NCHUNK; ++c) {
            const int s = c & 1;
            bar_sync(s ? FULL1 : FULL0, THREADS);
#pragma unroll
            for (int sx = 0; sx < 4; ++sx) {
                const uint32_t koff = (uint32_t)(kw * 4 + sx) * 32u;
                unsigned af0[4], af1[4];
                unsigned bfA[4], bfB[4];
                ldsm4(bfA, bAddr[s][0] + koff);    // prime B pipeline first
                ldsm4(af0, aAddr[s][0] + koff);
                ldsm4(af1, aAddr[s][1] + koff);
#pragma unroll
                for (int bt = 0; bt < 4; ++bt) {
                    unsigned* cur = (bt & 1) ? bfB : bfA;
                    unsigned* nxt = (bt & 1) ? bfA : bfB;
                    if (bt < 3) ldsm4(nxt, bAddr[s][bt + 1] + koff);
                    const int nt0 = bt * 2, nt1 = bt * 2 + 1;
                    mma16(acc[0][nt0], af0[0], af0[1], af0[2], af0[3], cur[0], cur[2]);
                    mma16(acc[1][nt0], af1[0], af1[1], af1[2], af1[3], cur[0], cur[2]);
                    mma16(acc[0][nt1], af0[0], af0[1], af0[2], af0[3], cur[1], cur[3]);
                    mma16(acc[1][nt1], af1[0], af1[1], af1[2], af1[3], cur[1], cur[3]);
                }
            }
            bar_arrive(s ? EMPTY1 : EMPTY0, THREADS);
        }

        // ---- epilogue: sum k-split partials via smem, then STG ----
        bar_sync(CONS, 512);
        float4* sRed = reinterpret_cast<float4*>(sm + OFF_A0);   // 16*256 float4
        if (kw == 1) {
            const int idx = tid - 256;
#pragma unroll
            for (int mt = 0; mt < 2; ++mt)
#pragma unroll
                for (int nt = 0; nt < 8; ++nt) {
                    int q = mt * 8 + nt;
                    sRed[q * 256 + idx] = make_float4(acc[mt][nt][0], acc[mt][nt][1],
                                                      acc[mt][nt][2], acc[mt][nt][3]);
                }
        }
        bar_sync(CONS, 512);
        if (kw == 0) {
#pragma unroll
            for (int mt = 0; mt < 2; ++mt) {
#pragma unroll
                for (int nt = 0; nt < 8; ++nt) {
                    int q = mt * 8 + nt;
                    float4 p = sRed[q * 256 + tid];
                    float2 v0 = make_float2(acc[mt][nt][0] + p.x, acc[mt][nt][1] + p.y);
                    float2 v1 = make_float2(acc[mt][nt][2] + p.z, acc[mt][nt][3] + p.w);
                    const int rr = b0 + row_base + mt * 16 + l4;
                    const int cc = col_base + nt * 8 + k4 * 2;
                    *reinterpret_cast<float2*>(out + (size_t)rr * U_DIM + cc) = v0;
                    *reinterpret_cast<float2*>(out + (size_t)(rr + 8) * U_DIM + cc) = v1;
                }
            }
        }
    }
}

extern "C" void kernel_launch(void* const* d_in, const int* in_sizes, int n_in,
                              void* d_out, int out_size) {
    const float* embeds = (const float*)d_in[0];   // (16384, 39, 64)
    const float* W      = (const float*)d_in[1];   // (128, 64, 64)
    float* out          = (float*)d_out;           // (16384, 128)

    static int smem_set = 0;
    if (!smem_set) {
        cudaFuncSetAttribute(quad_kernel,
                             cudaFuncAttributeMaxDynamicSharedMemorySize, SMEM_BYTES);
        smem_set = 1;
    }

    prep_kernel<<<1024 + (U_DIM * KPAD) / 256, 256>>>(embeds, W);
    quad_kernel<<<B_TOTAL / BTILE, THREADS, SMEM_BYTES>>>(out);
}